// round 14
// baseline (speedup 1.0000x reference)
#include <cuda_runtime.h>
#include <cstdint>

// ---------------------------------------------------------------------------
// ViT patch-embed + QKV + attention (round 13)
//  - round 12 + term-major mma interleaving (asm volatile preserves source
//    order; previous order had 3-deep RAW chains into each accumulator)
//  - per-accumulator term order unchanged -> bit-identical results
// ---------------------------------------------------------------------------

namespace {
constexpr int B_    = 8;
constexpr int NTOK  = 1024;
constexpr int CDIM  = 588;
constexpr int NH    = 14;
constexpr int HD    = 42;
constexpr int MTOT  = B_ * NTOK;     // 8192
constexpr int QKVN  = 3 * CDIM;      // 1764
constexpr int BH    = B_ * NH;       // 112
constexpr float ATTN_SCALE = 0.125f;
constexpr int PAIRS = 304;
constexpr int NPAD1 = 640;
constexpr int NPAD2 = 1792;
constexpr int GEMM_BUF  = 7680;      // words: Ah 2560 | Al 2560 | Bh 1280 | Bl 1280
constexpr int GEMM_DSM  = 2 * GEMM_BUF * 4;
constexpr int ATTN_BUF  = 7040;      // words: Kh 1792 | Kl 1792 | Vh 1728 | Vl 1728
constexpr int ATTN_DSM  = 2 * ATTN_BUF * 4;
}

__device__ uint32_t g_pa_hi[MTOT * PAIRS];
__device__ uint32_t g_pa_lo[MTOT * PAIRS];
__device__ uint32_t g_ta_hi[MTOT * PAIRS];
__device__ uint32_t g_ta_lo[MTOT * PAIRS];
__device__ uint32_t g_wc_hi[NPAD1 * PAIRS];
__device__ uint32_t g_wc_lo[NPAD1 * PAIRS];
__device__ uint32_t g_wq_hi[NPAD2 * PAIRS];
__device__ uint32_t g_wq_lo[NPAD2 * PAIRS];
__device__ uint32_t g_qp_hi[BH * NTOK * 24];
__device__ uint32_t g_qp_lo[BH * NTOK * 24];
__device__ uint32_t g_kp_hi[BH * NTOK * 24];
__device__ uint32_t g_kp_lo[BH * NTOK * 24];
__device__ uint16_t g_vh16[BH * 48 * NTOK];
__device__ uint16_t g_vl16[BH * 48 * NTOK];

// ---------------------------------------------------------------------------
__device__ __forceinline__ uint32_t pack_bf16x2(float vlo, float vhi) {
    uint32_t r;
    asm("cvt.rn.bf16x2.f32 %0, %1, %2;" : "=r"(r) : "f"(vhi), "f"(vlo));
    return r;
}
__device__ __forceinline__ void split_pair(float v0, float v1,
                                           uint32_t& hw, uint32_t& lw) {
    hw = pack_bf16x2(v0, v1);
    float r0 = v0 - __uint_as_float(hw << 16);
    float r1 = v1 - __uint_as_float(hw & 0xffff0000u);
    lw = pack_bf16x2(r0, r1);
}
__device__ __forceinline__ void mma_bf16(float* d, const uint32_t* a, const uint32_t* b) {
    asm volatile(
        "mma.sync.aligned.m16n8k16.row.col.f32.bf16.bf16.f32 "
        "{%0,%1,%2,%3}, {%4,%5,%6,%7}, {%8,%9}, {%0,%1,%2,%3};"
        : "+f"(d[0]), "+f"(d[1]), "+f"(d[2]), "+f"(d[3])
        : "r"(a[0]), "r"(a[1]), "r"(a[2]), "r"(a[3]), "r"(b[0]), "r"(b[1]));
}
__device__ __forceinline__ void ldsm_x4(uint32_t* r, uint32_t saddr) {
    asm volatile("ldmatrix.sync.aligned.m8n8.x4.shared.b16 {%0,%1,%2,%3}, [%4];"
        : "=r"(r[0]), "=r"(r[1]), "=r"(r[2]), "=r"(r[3]) : "r"(saddr));
}
__device__ __forceinline__ void cp16(void* s, const void* g) {
    uint32_t sa = (uint32_t)__cvta_generic_to_shared(s);
    asm volatile("cp.async.cg.shared.global [%0], [%1], 16;" :: "r"(sa), "l"(g));
}
__device__ __forceinline__ void cp_commit() {
    asm volatile("cp.async.commit_group;");
}
template<int N>
__device__ __forceinline__ void cp_wait() {
    asm volatile("cp.async.wait_group %0;" :: "n"(N));
}

// ---------------------------------------------------------------------------
// Patchify + split; grid (32 m-chunks x 256 m each? no: block = 256 threads,
// gridDim.x = MTOT, thread p covers pairs [0,294) in strides of 256 -> no div.
// ---------------------------------------------------------------------------
__global__ __launch_bounds__(256) void patch_split_k(const float* __restrict__ x) {
    int m = blockIdx.x;
    int b  = m >> 10;
    int sp = m & 1023;
    int py = sp >> 5;
    int px = sp & 31;
    const float* xb = x + ((size_t)b * 3 * 448 + py * 14) * 448 + px * 14;
    for (int p = threadIdx.x; p < 294; p += 256) {
        float v[2];
        #pragma unroll
        for (int e = 0; e < 2; e++) {
            int k = 2 * p + e;
            int c  = k / 196;
            int r2 = k - c * 196;
            int i  = r2 / 14;
            int j  = r2 - i * 14;
            v[e] = xb[((size_t)c * 448 + i) * 448 + j];
        }
        uint32_t hw, lw;
        split_pair(v[0], v[1], hw, lw);
        g_pa_hi[(size_t)m * PAIRS + p] = hw;
        g_pa_lo[(size_t)m * PAIRS + p] = lw;
    }
}

__global__ __launch_bounds__(256) void weight_split_k(const float* __restrict__ W,
                                                      int rows, int which) {
    int idx = blockIdx.x * 256 + threadIdx.x;
    if (idx >= rows * 294) return;
    int r = idx / 294;
    int p = idx - r * 294;
    float v0 = W[(size_t)r * CDIM + 2 * p];
    float v1 = W[(size_t)r * CDIM + 2 * p + 1];
    uint32_t hw, lw;
    split_pair(v0, v1, hw, lw);
    size_t o = (size_t)r * PAIRS + p;
    if (which == 0) { g_wc_hi[o] = hw; g_wc_lo[o] = lw; }
    else            { g_wq_hi[o] = hw; g_wq_lo[o] = lw; }
}

// ---------------------------------------------------------------------------
// bf16 GEMM, cp.async double buffer + ldmatrix + term-major mma order.
// ---------------------------------------------------------------------------
template<int NCOLS, bool SCATTER>
__global__ __launch_bounds__(256) void gemm_bf16_k(const float* __restrict__ bias) {
    extern __shared__ uint32_t dsm[];

    const uint32_t* __restrict__ Aph = SCATTER ? g_ta_hi : g_pa_hi;
    const uint32_t* __restrict__ Apl = SCATTER ? g_ta_lo : g_pa_lo;
    const uint32_t* __restrict__ Wph = SCATTER ? g_wq_hi : g_wc_hi;
    const uint32_t* __restrict__ Wpl = SCATTER ? g_wq_lo : g_wc_lo;

    int tid  = threadIdx.x;
    int lane = tid & 31;
    int wid  = tid >> 5;
    int g = lane >> 2, t = lane & 3;
    int wm0 = (wid >> 1) << 5;
    int wn0 = (wid & 1) << 5;
    int m0 = blockIdx.y << 7, n0 = blockIdx.x << 6;

    int ar = tid >> 2;
    int aq = (tid & 3) << 2;

    uint32_t a_off = (uint32_t)(((lane & 15) * 20 + ((lane >> 4) << 2)) * 4);
    uint32_t b_off = (uint32_t)(((((lane & 7) + ((lane >> 4) << 3))) * 20 +
                                 (((lane >> 3) & 1) << 2)) * 4);

    float acc[2][4][4] = {};

    auto load_tile = [&](int s, int b) {
        uint32_t* buf = dsm + b * GEMM_BUF;
        int k0p = s << 4;
        #pragma unroll
        for (int i = 0; i < 2; i++) {
            int idx = tid + (i << 8);
            int row = idx >> 2, q = (idx & 3) << 2;
            size_t ga = (size_t)(m0 + row) * PAIRS + k0p + q;
            cp16(&buf[row * 20 + q],        &Aph[ga]);
            cp16(&buf[2560 + row * 20 + q], &Apl[ga]);
        }
        size_t gb = (size_t)(n0 + ar) * PAIRS + k0p + aq;
        cp16(&buf[5120 + ar * 20 + aq], &Wph[gb]);
        cp16(&buf[6400 + ar * 20 + aq], &Wpl[gb]);
    };

    load_tile(0, 0);
    cp_commit();

    for (int s = 0; s < 19; s++) {
        if (s < 18) { load_tile(s + 1, (s + 1) & 1); cp_commit(); }
        if (s < 18) cp_wait<1>(); else cp_wait<0>();
        __syncthreads();

        uint32_t sb = (uint32_t)__cvta_generic_to_shared(dsm + (s & 1) * GEMM_BUF);
        uint32_t sAh = sb,             sAl = sb + 2560 * 4;
        uint32_t sBh = sb + 5120 * 4,  sBl = sb + 6400 * 4;

        #pragma unroll
        for (int kk = 0; kk < 2; kk++) {
            uint32_t kb = kk * 32;
            uint32_t aH[2][4], aL[2][4];
            #pragma unroll
            for (int mi = 0; mi < 2; mi++) {
                uint32_t rb = (uint32_t)((wm0 + (mi << 4)) * 80);
                ldsm_x4(aH[mi], sAh + rb + a_off + kb);
                ldsm_x4(aL[mi], sAl + rb + a_off + kb);
            }
            uint32_t bH[8], bL[8];
            #pragma unroll
            for (int gq = 0; gq < 2; gq++) {
                uint32_t nb = (uint32_t)((wn0 + (gq << 4)) * 80);
                ldsm_x4(&bH[gq * 4], sBh + nb + b_off + kb);
                ldsm_x4(&bL[gq * 4], sBl + nb + b_off + kb);
            }
            // term-major: same-accumulator reuse spaced 8 apart
            #pragma unroll
            for (int mi = 0; mi < 2; mi++)
                #pragma unroll
                for (int ni = 0; ni < 4; ni++)
                    mma_bf16(acc[mi][ni], aL[mi], &bH[ni * 2]);
            #pragma unroll
            for (int mi = 0; mi < 2; mi++)
                #pragma unroll
                for (int ni = 0; ni < 4; ni++)
                    mma_bf16(acc[mi][ni], aH[mi], &bL[ni * 2]);
            #pragma unroll
            for (int mi = 0; mi < 2; mi++)
                #pragma unroll
                for (int ni = 0; ni < 4; ni++)
                    mma_bf16(acc[mi][ni], aH[mi], &bH[ni * 2]);
        }
        __syncthreads();
    }

    #pragma unroll
    for (int mi = 0; mi < 2; mi++)
        #pragma unroll
        for (int rh = 0; rh < 2; rh++) {
            int m = m0 + wm0 + (mi << 4) + g + (rh << 3);
            int b = m >> 10, n = m & 1023;
            #pragma unroll
            for (int ni = 0; ni < 4; ni++) {
                int o = n0 + wn0 + (ni << 3) + 2 * t;
                if (o >= NCOLS) continue;
                float v0 = acc[mi][ni][rh * 2 + 0] + bias[o];
                float v1 = acc[mi][ni][rh * 2 + 1] + bias[o + 1];
                if (!SCATTER) {
                    uint32_t hw, lw;
                    split_pair(v0, v1, hw, lw);
                    size_t tb = (size_t)m * PAIRS + (o >> 1);
                    g_ta_hi[tb] = hw;
                    g_ta_lo[tb] = lw;
                } else {
                    int sgrp = o / CDIM;
                    int cc   = o - sgrp * CDIM;
                    int h    = cc / HD;
                    int d    = cc - h * HD;
                    int bh   = b * NH + h;
                    if (sgrp < 2) {
                        uint32_t hw, lw;
                        split_pair(v0, v1, hw, lw);
                        size_t base = ((size_t)bh * NTOK + n) * 24 + (d >> 1);
                        if (sgrp == 0) { g_qp_hi[base] = hw; g_qp_lo[base] = lw; }
                        else           { g_kp_hi[base] = hw; g_kp_lo[base] = lw; }
                    } else {
                        #pragma unroll
                        for (int e = 0; e < 2; e++) {
                            float val = e ? v1 : v0;
                            uint16_t hb;
                            asm("cvt.rn.bf16.f32 %0, %1;" : "=h"(hb) : "f"(val));
                            float rv = val - __uint_as_float((uint32_t)hb << 16);
                            uint16_t lb;
                            asm("cvt.rn.bf16.f32 %0, %1;" : "=h"(lb) : "f"(rv));
                            size_t vo = ((size_t)bh * 48 + d + e) * NTOK + n;
                            g_vh16[vo] = hb; g_vl16[vo] = lb;
                        }
                    }
                }
            }
        }
}

// ---------------------------------------------------------------------------
// bf16 flash attention + ldmatrix + term-major mma order.
// ---------------------------------------------------------------------------
__global__ __launch_bounds__(256) void attn_k(float* __restrict__ out) {
    extern __shared__ uint32_t dsm[];

    int tid  = threadIdx.x;
    int lane = tid & 31, w = tid >> 5;
    int g = lane >> 2, t = lane & 3;
    int wm = w << 4;
    int bh = blockIdx.y;
    int r0 = blockIdx.x << 7;

    uint32_t k_off = (uint32_t)((((lane & 7) + ((lane >> 4) << 3)) * 28 +
                                 (((lane >> 3) & 1) << 2)) * 4);
    uint32_t v_off = (uint32_t)((((lane & 7) + ((lane >> 4) << 3)) * 36 +
                                 (((lane >> 3) & 1) << 2)) * 4);

    uint32_t qH[3][4], qL[3][4];
    {
        size_t qb0 = ((size_t)bh * NTOK + r0 + wm + g) * 24;
        size_t qb8 = qb0 + 8 * 24;
        #pragma unroll
        for (int kk = 0; kk < 3; kk++) {
            int kp0 = 8 * kk + t, kp1 = kp0 + 4;
            qH[kk][0] = g_qp_hi[qb0 + kp0]; qH[kk][1] = g_qp_hi[qb8 + kp0];
            qH[kk][2] = g_qp_hi[qb0 + kp1]; qH[kk][3] = g_qp_hi[qb8 + kp1];
            qL[kk][0] = g_qp_lo[qb0 + kp0]; qL[kk][1] = g_qp_lo[qb8 + kp0];
            qL[kk][2] = g_qp_lo[qb0 + kp1]; qL[kk][3] = g_qp_lo[qb8 + kp1];
        }
    }

    auto load_tile = [&](int c0, int b) {
        uint32_t* kh = dsm + b * ATTN_BUF;
        uint32_t* kl = kh + 1792;
        uint32_t* vh = kh + 3584;
        uint32_t* vl = kh + 5312;
        #pragma unroll
        for (int i = 0; i < 3; i++) {
            int idx = tid + (i << 8);
            int pl  = idx >= 384;
            int j   = pl ? idx - 384 : idx;
            int row = j / 6, q = (j % 6) << 2;
            const uint32_t* src =
                (pl ? g_kp_lo : g_kp_hi) + ((size_t)bh * NTOK + c0 + row) * 24 + q;
            uint32_t* dst = (pl ? kl : kh) + row * 28 + q;
            cp16(dst, src);
        }
        #pragma unroll
        for (int i = 0; i < 3; i++) {
            int idx = tid + (i << 8);
            int pl  = idx >= 384;
            int j   = pl ? idx - 384 : idx;
            int row = j >> 3, q = (j & 7) << 2;
            const uint16_t* src =
                (pl ? g_vl16 : g_vh16) + ((size_t)bh * 48 + row) * NTOK + c0 + (q << 1);
            uint32_t* dst = (pl ? vl : vh) + row * 36 + q;
            cp16(dst, src);
        }
    };

    float m0r = -1e30f, m1r = -1e30f, l0r = 0.f, l1r = 0.f;
    float o[6][4] = {};

    load_tile(0, 0);
    cp_commit();

    for (int it = 0; it < 16; it++) {
        if (it < 15) { load_tile((it + 1) << 6, (it + 1) & 1); cp_commit(); }
        if (it < 15) cp_wait<1>(); else cp_wait<0>();
        __syncthreads();

        uint32_t sb = (uint32_t)__cvta_generic_to_shared(dsm + (it & 1) * ATTN_BUF);
        uint32_t sKh = sb,             sKl = sb + 1792 * 4;
        uint32_t sVh = sb + 3584 * 4,  sVl = sb + 5312 * 4;

        // --- S = Q K^T (term-major; reuse spacing 8) ---
        float s[8][4] = {};
        #pragma unroll
        for (int kk = 0; kk < 3; kk++) {
            uint32_t kb = kk * 32;
            uint32_t bH[4][4], bL[4][4];
            #pragma unroll
            for (int np = 0; np < 4; np++) {
                uint32_t nb = (uint32_t)(np * 16 * 28 * 4);
                ldsm_x4(bH[np], sKh + nb + k_off + kb);
                ldsm_x4(bL[np], sKl + nb + k_off + kb);
            }
            #pragma unroll
            for (int np = 0; np < 4; np++) {
                mma_bf16(s[2 * np],     qL[kk], &bH[np][0]);
                mma_bf16(s[2 * np + 1], qL[kk], &bH[np][2]);
            }
            #pragma unroll
            for (int np = 0; np < 4; np++) {
                mma_bf16(s[2 * np],     qH[kk], &bL[np][0]);
                mma_bf16(s[2 * np + 1], qH[kk], &bL[np][2]);
            }
            #pragma unroll
            for (int np = 0; np < 4; np++) {
                mma_bf16(s[2 * np],     qH[kk], &bH[np][0]);
                mma_bf16(s[2 * np + 1], qH[kk], &bH[np][2]);
            }
        }

        // --- warp-private online softmax ---
        float pm0 = -1e30f, pm1 = -1e30f;
        #pragma unroll
        for (int nb = 0; nb < 8; nb++) {
            s[nb][0] *= ATTN_SCALE; s[nb][1] *= ATTN_SCALE;
            s[nb][2] *= ATTN_SCALE; s[nb][3] *= ATTN_SCALE;
            pm0 = fmaxf(pm0, fmaxf(s[nb][0], s[nb][1]));
            pm1 = fmaxf(pm1, fmaxf(s[nb][2], s[nb][3]));
        }
        pm0 = fmaxf(pm0, __shfl_xor_sync(0xffffffffu, pm0, 1));
        pm0 = fmaxf(pm0, __shfl_xor_sync(0xffffffffu, pm0, 2));
        pm1 = fmaxf(pm1, __shfl_xor_sync(0xffffffffu, pm1, 1));
        pm1 = fmaxf(pm1, __shfl_xor_sync(0xffffffffu, pm1, 2));

        float mn0 = fmaxf(m0r, pm0);
        float mn1 = fmaxf(m1r, pm1);
        float al0 = __expf(m0r - mn0), al1 = __expf(m1r - mn1);
        m0r = mn0; m1r = mn1;

        float ps0 = 0.f, ps1 = 0.f;
        #pragma unroll
        for (int nb = 0; nb < 8; nb++) {
            s[nb][0] = __expf(s[nb][0] - mn0); s[nb][1] = __expf(s[nb][1] - mn0);
            s[nb][2] = __expf(s[nb][2] - mn1); s[nb][3] = __expf(s[nb][3] - mn1);
            ps0 += s[nb][0] + s[nb][1];
            ps1 += s[nb][2] + s[nb][3];
        }
        ps0 += __shfl_xor_sync(0xffffffffu, ps0, 1);
        ps0 += __shfl_xor_sync(0xffffffffu, ps0, 2);
        ps1 += __shfl_xor_sync(0xffffffffu, ps1, 1);
        ps1 += __shfl_xor_sync(0xffffffffu, ps1, 2);
        l0r = l0r * al0 + ps0;
        l1r = l1r * al1 + ps1;

        #pragma unroll
        for (int f = 0; f < 6; f++) {
            o[f][0] *= al0; o[f][1] *= al0; o[f][2] *= al1; o[f][3] *= al1;
        }

        // --- O += P V (term-major; reuse spacing 6) ---
        #pragma unroll
        for (int kk = 0; kk < 4; kk++) {
            uint32_t pH[4], pL[4];
            split_pair(s[2 * kk][0],     s[2 * kk][1],     pH[0], pL[0]);
            split_pair(s[2 * kk][2],     s[2 * kk][3],     pH[1], pL[1]);
            split_pair(s[2 * kk + 1][0], s[2 * kk + 1][1], pH[2], pL[2]);
            split_pair(s[2 * kk + 1][2], s[2 * kk + 1][3], pH[3], pL[3]);
            uint32_t kb = kk * 32;
            uint32_t bH[3][4], bL[3][4];
            #pragma unroll
            for (int np = 0; np < 3; np++) {
                uint32_t db = (uint32_t)(np * 16 * 36 * 4);
                ldsm_x4(bH[np], sVh + db + v_off + kb);
                ldsm_x4(bL[np], sVl + db + v_off + kb);
            }
            #pragma unroll
            for (int np = 0; np < 3; np++) {
                mma_bf16(o[2 * np],     pL, &bH[np][0]);
                mma_bf16(o[2 * np + 1], pL, &bH[np][2]);
            }
            #pragma unroll
            for (int np = 0; np < 3; np++) {
                mma_bf16(o[2 * np],     pH, &bL[np][0]);
                mma_bf16(o[2 * np + 1], pH, &bL[np][2]);
            }
            #pragma unroll
            for (int np = 0; np < 3; np++) {
                mma_bf16(o[2 * np],     pH, &bH[np][0]);
                mma_bf16(o[2 * np + 1], pH, &bH[np][2]);
            }
        }
        __syncthreads();
    }

    int b = bh / NH, h = bh - b * NH;
    float inv0 = 1.f / l0r, inv1 = 1.f / l1r;
    size_t row0 = (size_t)(b * NTOK + r0 + wm + g) * CDIM + h * HD;
    size_t row1 = (size_t)(b * NTOK + r0 + wm + 8 + g) * CDIM + h * HD;
    #pragma unroll
    for (int nb = 0; nb < 6; nb++) {
        int d = (nb << 3) + 2 * t;
        if (d < HD)     out[row0 + d]     = o[nb][0] * inv0;
        if (d + 1 < HD) out[row0 + d + 1] = o[nb][1] * inv0;
        if (d < HD)     out[row1 + d]     = o[nb][2] * inv1;
        if (d + 1 < HD) out[row1 + d + 1] = o[nb][3] * inv1;
    }
}

// ---------------------------------------------------------------------------
extern "C" void kernel_launch(void* const* d_in, const int* in_sizes, int n_in,
                              void* d_out, int out_size) {
    const float* x      = (const float*)d_in[0];
    const float* conv_w = (const float*)d_in[1];
    const float* conv_b = (const float*)d_in[2];
    const float* qkv_w  = (const float*)d_in[3];
    const float* qkv_b  = (const float*)d_in[4];
    float* out = (float*)d_out;

    cudaFuncSetAttribute(gemm_bf16_k<CDIM, false>,
                         cudaFuncAttributeMaxDynamicSharedMemorySize, GEMM_DSM);
    cudaFuncSetAttribute(gemm_bf16_k<QKVN, true>,
                         cudaFuncAttributeMaxDynamicSharedMemorySize, GEMM_DSM);
    cudaFuncSetAttribute(attn_k,
                         cudaFuncAttributeMaxDynamicSharedMemorySize, ATTN_DSM);

    patch_split_k<<<MTOT, 256>>>(x);
    weight_split_k<<<(CDIM * 294 + 255) / 256, 256>>>(conv_w, CDIM, 0);
    weight_split_k<<<(QKVN * 294 + 255) / 256, 256>>>(qkv_w, QKVN, 1);
    gemm_bf16_k<CDIM, false><<<dim3(NPAD1 / 64, MTOT / 128), 256, GEMM_DSM>>>(conv_b);
    gemm_bf16_k<QKVN, true ><<<dim3(NPAD2 / 64, MTOT / 128), 256, GEMM_DSM>>>(qkv_b);
    attn_k<<<dim3(NTOK / 128, BH), 256, ATTN_DSM>>>(out);
}

// round 17
// speedup vs baseline: 1.0123x; 1.0123x over previous
#include <cuda_runtime.h>
#include <cstdint>

// ---------------------------------------------------------------------------
// ViT patch-embed + QKV + attention (round 15)
//  - base = round 12 (tcgen05 unavailable: harness PTX targets compute_103,
//    no 'a' feature -> legacy mma.sync is the only tensor path)
//  - GEMM tile widened to 128x128, warp tile 32x64: mma:ldsm 4:1,
//    16 accumulators/warp, A L2 traffic halved
// ---------------------------------------------------------------------------

namespace {
constexpr int B_    = 8;
constexpr int NTOK  = 1024;
constexpr int CDIM  = 588;
constexpr int NH    = 14;
constexpr int HD    = 42;
constexpr int MTOT  = B_ * NTOK;     // 8192
constexpr int QKVN  = 3 * CDIM;      // 1764
constexpr int BH    = B_ * NH;       // 112
constexpr float ATTN_SCALE = 0.125f;
constexpr int PAIRS = 304;           // k-pairs per row, K padded 588 -> 608
constexpr int NPAD1 = 640;
constexpr int NPAD2 = 1792;
// gemm: per buffer Ah|Al|Bh|Bl each 128 rows x 20 words = 2560 words
constexpr int GEMM_BUF  = 10240;
constexpr int GEMM_DSM  = 2 * GEMM_BUF * 4;   // 81920 B
constexpr int ATTN_BUF  = 7040;      // words: Kh 1792 | Kl 1792 | Vh 1728 | Vl 1728
constexpr int ATTN_DSM  = 2 * ATTN_BUF * 4;
}

__device__ uint32_t g_pa_hi[MTOT * PAIRS];
__device__ uint32_t g_pa_lo[MTOT * PAIRS];
__device__ uint32_t g_ta_hi[MTOT * PAIRS];
__device__ uint32_t g_ta_lo[MTOT * PAIRS];
__device__ uint32_t g_wc_hi[NPAD1 * PAIRS];
__device__ uint32_t g_wc_lo[NPAD1 * PAIRS];
__device__ uint32_t g_wq_hi[NPAD2 * PAIRS];
__device__ uint32_t g_wq_lo[NPAD2 * PAIRS];
__device__ uint32_t g_qp_hi[BH * NTOK * 24];
__device__ uint32_t g_qp_lo[BH * NTOK * 24];
__device__ uint32_t g_kp_hi[BH * NTOK * 24];
__device__ uint32_t g_kp_lo[BH * NTOK * 24];
__device__ uint16_t g_vh16[BH * 48 * NTOK];
__device__ uint16_t g_vl16[BH * 48 * NTOK];

// ---------------------------------------------------------------------------
__device__ __forceinline__ uint32_t pack_bf16x2(float vlo, float vhi) {
    uint32_t r;
    asm("cvt.rn.bf16x2.f32 %0, %1, %2;" : "=r"(r) : "f"(vhi), "f"(vlo));
    return r;
}
__device__ __forceinline__ void split_pair(float v0, float v1,
                                           uint32_t& hw, uint32_t& lw) {
    hw = pack_bf16x2(v0, v1);
    float r0 = v0 - __uint_as_float(hw << 16);
    float r1 = v1 - __uint_as_float(hw & 0xffff0000u);
    lw = pack_bf16x2(r0, r1);
}
__device__ __forceinline__ void mma_bf16(float* d, const uint32_t* a, const uint32_t* b) {
    asm volatile(
        "mma.sync.aligned.m16n8k16.row.col.f32.bf16.bf16.f32 "
        "{%0,%1,%2,%3}, {%4,%5,%6,%7}, {%8,%9}, {%0,%1,%2,%3};"
        : "+f"(d[0]), "+f"(d[1]), "+f"(d[2]), "+f"(d[3])
        : "r"(a[0]), "r"(a[1]), "r"(a[2]), "r"(a[3]), "r"(b[0]), "r"(b[1]));
}
__device__ __forceinline__ void ldsm_x4(uint32_t* r, uint32_t saddr) {
    asm volatile("ldmatrix.sync.aligned.m8n8.x4.shared.b16 {%0,%1,%2,%3}, [%4];"
        : "=r"(r[0]), "=r"(r[1]), "=r"(r[2]), "=r"(r[3]) : "r"(saddr));
}
__device__ __forceinline__ void cp16(void* s, const void* g) {
    uint32_t sa = (uint32_t)__cvta_generic_to_shared(s);
    asm volatile("cp.async.cg.shared.global [%0], [%1], 16;" :: "r"(sa), "l"(g));
}
__device__ __forceinline__ void cp_commit() {
    asm volatile("cp.async.commit_group;");
}
template<int N>
__device__ __forceinline__ void cp_wait() {
    asm volatile("cp.async.wait_group %0;" :: "n"(N));
}

// ---------------------------------------------------------------------------
__global__ __launch_bounds__(256) void patch_split_k(const float* __restrict__ x) {
    int m = blockIdx.x;
    int b  = m >> 10;
    int sp = m & 1023;
    int py = sp >> 5;
    int px = sp & 31;
    const float* xb = x + ((size_t)b * 3 * 448 + py * 14) * 448 + px * 14;
    for (int p = threadIdx.x; p < 294; p += 256) {
        float v[2];
        #pragma unroll
        for (int e = 0; e < 2; e++) {
            int k = 2 * p + e;
            int c  = k / 196;
            int r2 = k - c * 196;
            int i  = r2 / 14;
            int j  = r2 - i * 14;
            v[e] = xb[((size_t)c * 448 + i) * 448 + j];
        }
        uint32_t hw, lw;
        split_pair(v[0], v[1], hw, lw);
        g_pa_hi[(size_t)m * PAIRS + p] = hw;
        g_pa_lo[(size_t)m * PAIRS + p] = lw;
    }
}

__global__ __launch_bounds__(256) void weight_split_k(const float* __restrict__ W,
                                                      int rows, int which) {
    int idx = blockIdx.x * 256 + threadIdx.x;
    if (idx >= rows * 294) return;
    int r = idx / 294;
    int p = idx - r * 294;
    float v0 = W[(size_t)r * CDIM + 2 * p];
    float v1 = W[(size_t)r * CDIM + 2 * p + 1];
    uint32_t hw, lw;
    split_pair(v0, v1, hw, lw);
    size_t o = (size_t)r * PAIRS + p;
    if (which == 0) { g_wc_hi[o] = hw; g_wc_lo[o] = lw; }
    else            { g_wq_hi[o] = hw; g_wq_lo[o] = lw; }
}

// ---------------------------------------------------------------------------
// bf16 GEMM, 128x128 CTA tile, warp tile 32x64, cp.async double buffer,
// ldmatrix fragments. buffer (words): Ah[0,2560) Al[2560,5120)
// Bh[5120,7680) Bl[7680,10240).
// ---------------------------------------------------------------------------
template<int NCOLS, bool SCATTER>
__global__ __launch_bounds__(256) void gemm_bf16_k(const float* __restrict__ bias) {
    extern __shared__ uint32_t dsm[];

    const uint32_t* __restrict__ Aph = SCATTER ? g_ta_hi : g_pa_hi;
    const uint32_t* __restrict__ Apl = SCATTER ? g_ta_lo : g_pa_lo;
    const uint32_t* __restrict__ Wph = SCATTER ? g_wq_hi : g_wc_hi;
    const uint32_t* __restrict__ Wpl = SCATTER ? g_wq_lo : g_wc_lo;

    int tid  = threadIdx.x;
    int lane = tid & 31;
    int wid  = tid >> 5;
    int g = lane >> 2, t = lane & 3;
    int wm0 = (wid >> 1) << 5;        // 0,32,64,96
    int wn0 = (wid & 1) << 6;         // 0,64
    int m0 = blockIdx.y << 7, n0 = blockIdx.x << 7;

    uint32_t a_off = (uint32_t)(((lane & 15) * 20 + ((lane >> 4) << 2)) * 4);
    uint32_t b_off = (uint32_t)(((((lane & 7) + ((lane >> 4) << 3))) * 20 +
                                 (((lane >> 3) & 1) << 2)) * 4);

    float acc[2][8][4] = {};

    auto load_tile = [&](int s, int b) {
        uint32_t* buf = dsm + b * GEMM_BUF;
        int k0p = s << 4;
        #pragma unroll
        for (int i = 0; i < 2; i++) {
            int idx = tid + (i << 8);       // 0..511
            int row = idx >> 2, q = (idx & 3) << 2;
            size_t ga = (size_t)(m0 + row) * PAIRS + k0p + q;
            size_t gb = (size_t)(n0 + row) * PAIRS + k0p + q;
            cp16(&buf[row * 20 + q],        &Aph[ga]);
            cp16(&buf[2560 + row * 20 + q], &Apl[ga]);
            cp16(&buf[5120 + row * 20 + q], &Wph[gb]);
            cp16(&buf[7680 + row * 20 + q], &Wpl[gb]);
        }
    };

    load_tile(0, 0);
    cp_commit();

    for (int s = 0; s < 19; s++) {
        if (s < 18) { load_tile(s + 1, (s + 1) & 1); cp_commit(); }
        if (s < 18) cp_wait<1>(); else cp_wait<0>();
        __syncthreads();

        uint32_t sb = (uint32_t)__cvta_generic_to_shared(dsm + (s & 1) * GEMM_BUF);
        uint32_t sAh = sb,             sAl = sb + 2560 * 4;
        uint32_t sBh = sb + 5120 * 4,  sBl = sb + 7680 * 4;

        #pragma unroll
        for (int kk = 0; kk < 2; kk++) {
            uint32_t kb = kk * 32;
            uint32_t aH[2][4], aL[2][4];
            #pragma unroll
            for (int mi = 0; mi < 2; mi++) {
                uint32_t rb = (uint32_t)((wm0 + (mi << 4)) * 80);
                ldsm_x4(aH[mi], sAh + rb + a_off + kb);
                ldsm_x4(aL[mi], sAl + rb + a_off + kb);
            }
            #pragma unroll
            for (int gq = 0; gq < 4; gq++) {   // 16 n-cols per gq (2 octets)
                uint32_t nb = (uint32_t)((wn0 + (gq << 4)) * 80);
                uint32_t bH[4], bL[4];
                ldsm_x4(bH, sBh + nb + b_off + kb);
                ldsm_x4(bL, sBl + nb + b_off + kb);
                #pragma unroll
                for (int mi = 0; mi < 2; mi++)
                    #pragma unroll
                    for (int oc = 0; oc < 2; oc++) {
                        float* a4 = acc[mi][gq * 2 + oc];
                        mma_bf16(a4, aL[mi], &bH[oc * 2]);
                        mma_bf16(a4, aH[mi], &bL[oc * 2]);
                        mma_bf16(a4, aH[mi], &bH[oc * 2]);
                    }
            }
        }
        __syncthreads();
    }

    #pragma unroll
    for (int mi = 0; mi < 2; mi++)
        #pragma unroll
        for (int rh = 0; rh < 2; rh++) {
            int m = m0 + wm0 + (mi << 4) + g + (rh << 3);
            int b = m >> 10, n = m & 1023;
            #pragma unroll
            for (int ni = 0; ni < 8; ni++) {
                int o = n0 + wn0 + (ni << 3) + 2 * t;
                if (o >= NCOLS) continue;
                float v0 = acc[mi][ni][rh * 2 + 0] + bias[o];
                float v1 = acc[mi][ni][rh * 2 + 1] + bias[o + 1];
                if (!SCATTER) {
                    uint32_t hw, lw;
                    split_pair(v0, v1, hw, lw);
                    size_t tb = (size_t)m * PAIRS + (o >> 1);
                    g_ta_hi[tb] = hw;
                    g_ta_lo[tb] = lw;
                } else {
                    int sgrp = (o >= 2 * CDIM) ? 2 : ((o >= CDIM) ? 1 : 0);
                    int cc   = o - sgrp * CDIM;
                    int h    = cc / HD;
                    int d    = cc - h * HD;
                    int bh   = b * NH + h;
                    if (sgrp < 2) {
                        uint32_t hw, lw;
                        split_pair(v0, v1, hw, lw);
                        size_t base = ((size_t)bh * NTOK + n) * 24 + (d >> 1);
                        if (sgrp == 0) { g_qp_hi[base] = hw; g_qp_lo[base] = lw; }
                        else           { g_kp_hi[base] = hw; g_kp_lo[base] = lw; }
                    } else {
                        #pragma unroll
                        for (int e = 0; e < 2; e++) {
                            float val = e ? v1 : v0;
                            uint16_t hb;
                            asm("cvt.rn.bf16.f32 %0, %1;" : "=h"(hb) : "f"(val));
                            float rv = val - __uint_as_float((uint32_t)hb << 16);
                            uint16_t lb;
                            asm("cvt.rn.bf16.f32 %0, %1;" : "=h"(lb) : "f"(rv));
                            size_t vo = ((size_t)bh * 48 + d + e) * NTOK + n;
                            g_vh16[vo] = hb; g_vl16[vo] = lb;
                        }
                    }
                }
            }
        }
}

// ---------------------------------------------------------------------------
// bf16 flash attention (round 12, unchanged)
// ---------------------------------------------------------------------------
__global__ __launch_bounds__(256) void attn_k(float* __restrict__ out) {
    extern __shared__ uint32_t dsm[];

    int tid  = threadIdx.x;
    int lane = tid & 31, w = tid >> 5;
    int g = lane >> 2, t = lane & 3;
    int wm = w << 4;
    int bh = blockIdx.y;
    int r0 = blockIdx.x << 7;

    uint32_t k_off = (uint32_t)((((lane & 7) + ((lane >> 4) << 3)) * 28 +
                                 (((lane >> 3) & 1) << 2)) * 4);
    uint32_t v_off = (uint32_t)((((lane & 7) + ((lane >> 4) << 3)) * 36 +
                                 (((lane >> 3) & 1) << 2)) * 4);

    uint32_t qH[3][4], qL[3][4];
    {
        size_t qb0 = ((size_t)bh * NTOK + r0 + wm + g) * 24;
        size_t qb8 = qb0 + 8 * 24;
        #pragma unroll
        for (int kk = 0; kk < 3; kk++) {
            int kp0 = 8 * kk + t, kp1 = kp0 + 4;
            qH[kk][0] = g_qp_hi[qb0 + kp0]; qH[kk][1] = g_qp_hi[qb8 + kp0];
            qH[kk][2] = g_qp_hi[qb0 + kp1]; qH[kk][3] = g_qp_hi[qb8 + kp1];
            qL[kk][0] = g_qp_lo[qb0 + kp0]; qL[kk][1] = g_qp_lo[qb8 + kp0];
            qL[kk][2] = g_qp_lo[qb0 + kp1]; qL[kk][3] = g_qp_lo[qb8 + kp1];
        }
    }

    auto load_tile = [&](int c0, int b) {
        uint32_t* kh = dsm + b * ATTN_BUF;
        uint32_t* kl = kh + 1792;
        uint32_t* vh = kh + 3584;
        uint32_t* vl = kh + 5312;
        #pragma unroll
        for (int i = 0; i < 3; i++) {
            int idx = tid + (i << 8);
            int pl  = idx >= 384;
            int j   = pl ? idx - 384 : idx;
            int row = j / 6, q = (j % 6) << 2;
            const uint32_t* src =
                (pl ? g_kp_lo : g_kp_hi) + ((size_t)bh * NTOK + c0 + row) * 24 + q;
            uint32_t* dst = (pl ? kl : kh) + row * 28 + q;
            cp16(dst, src);
        }
        #pragma unroll
        for (int i = 0; i < 3; i++) {
            int idx = tid + (i << 8);
            int pl  = idx >= 384;
            int j   = pl ? idx - 384 : idx;
            int row = j >> 3, q = (j & 7) << 2;
            const uint16_t* src =
                (pl ? g_vl16 : g_vh16) + ((size_t)bh * 48 + row) * NTOK + c0 + (q << 1);
            uint32_t* dst = (pl ? vl : vh) + row * 36 + q;
            cp16(dst, src);
        }
    };

    float m0r = -1e30f, m1r = -1e30f, l0r = 0.f, l1r = 0.f;
    float o[6][4] = {};

    load_tile(0, 0);
    cp_commit();

    for (int it = 0; it < 16; it++) {
        if (it < 15) { load_tile((it + 1) << 6, (it + 1) & 1); cp_commit(); }
        if (it < 15) cp_wait<1>(); else cp_wait<0>();
        __syncthreads();

        uint32_t sb = (uint32_t)__cvta_generic_to_shared(dsm + (it & 1) * ATTN_BUF);
        uint32_t sKh = sb,             sKl = sb + 1792 * 4;
        uint32_t sVh = sb + 3584 * 4,  sVl = sb + 5312 * 4;

        float s[8][4] = {};
        #pragma unroll
        for (int kk = 0; kk < 3; kk++) {
            uint32_t kb = kk * 32;
            #pragma unroll
            for (int np = 0; np < 4; np++) {
                uint32_t nb = (uint32_t)(np * 16 * 28 * 4);
                uint32_t bH[4], bL[4];
                ldsm_x4(bH, sKh + nb + k_off + kb);
                ldsm_x4(bL, sKl + nb + k_off + kb);
                mma_bf16(s[2 * np],     qL[kk], &bH[0]);
                mma_bf16(s[2 * np],     qH[kk], &bL[0]);
                mma_bf16(s[2 * np],     qH[kk], &bH[0]);
                mma_bf16(s[2 * np + 1], qL[kk], &bH[2]);
                mma_bf16(s[2 * np + 1], qH[kk], &bL[2]);
                mma_bf16(s[2 * np + 1], qH[kk], &bH[2]);
            }
        }

        float pm0 = -1e30f, pm1 = -1e30f;
        #pragma unroll
        for (int nb = 0; nb < 8; nb++) {
            s[nb][0] *= ATTN_SCALE; s[nb][1] *= ATTN_SCALE;
            s[nb][2] *= ATTN_SCALE; s[nb][3] *= ATTN_SCALE;
            pm0 = fmaxf(pm0, fmaxf(s[nb][0], s[nb][1]));
            pm1 = fmaxf(pm1, fmaxf(s[nb][2], s[nb][3]));
        }
        pm0 = fmaxf(pm0, __shfl_xor_sync(0xffffffffu, pm0, 1));
        pm0 = fmaxf(pm0, __shfl_xor_sync(0xffffffffu, pm0, 2));
        pm1 = fmaxf(pm1, __shfl_xor_sync(0xffffffffu, pm1, 1));
        pm1 = fmaxf(pm1, __shfl_xor_sync(0xffffffffu, pm1, 2));

        float mn0 = fmaxf(m0r, pm0);
        float mn1 = fmaxf(m1r, pm1);
        float al0 = __expf(m0r - mn0), al1 = __expf(m1r - mn1);
        m0r = mn0; m1r = mn1;

        float ps0 = 0.f, ps1 = 0.f;
        #pragma unroll
        for (int nb = 0; nb < 8; nb++) {
            s[nb][0] = __expf(s[nb][0] - mn0); s[nb][1] = __expf(s[nb][1] - mn0);
            s[nb][2] = __expf(s[nb][2] - mn1); s[nb][3] = __expf(s[nb][3] - mn1);
            ps0 += s[nb][0] + s[nb][1];
            ps1 += s[nb][2] + s[nb][3];
        }
        ps0 += __shfl_xor_sync(0xffffffffu, ps0, 1);
        ps0 += __shfl_xor_sync(0xffffffffu, ps0, 2);
        ps1 += __shfl_xor_sync(0xffffffffu, ps1, 1);
        ps1 += __shfl_xor_sync(0xffffffffu, ps1, 2);
        l0r = l0r * al0 + ps0;
        l1r = l1r * al1 + ps1;

        #pragma unroll
        for (int f = 0; f < 6; f++) {
            o[f][0] *= al0; o[f][1] *= al0; o[f][2] *= al1; o[f][3] *= al1;
        }

        #pragma unroll
        for (int kk = 0; kk < 4; kk++) {
            uint32_t pH[4], pL[4];
            split_pair(s[2 * kk][0],     s[2 * kk][1],     pH[0], pL[0]);
            split_pair(s[2 * kk][2],     s[2 * kk][3],     pH[1], pL[1]);
            split_pair(s[2 * kk + 1][0], s[2 * kk + 1][1], pH[2], pL[2]);
            split_pair(s[2 * kk + 1][2], s[2 * kk + 1][3], pH[3], pL[3]);
            uint32_t kb = kk * 32;
            #pragma unroll
            for (int np = 0; np < 3; np++) {
                uint32_t db = (uint32_t)(np * 16 * 36 * 4);
                uint32_t bH[4], bL[4];
                ldsm_x4(bH, sVh + db + v_off + kb);
                ldsm_x4(bL, sVl + db + v_off + kb);
                mma_bf16(o[2 * np],     pL, &bH[0]);
                mma_bf16(o[2 * np],     pH, &bL[0]);
                mma_bf16(o[2 * np],     pH, &bH[0]);
                mma_bf16(o[2 * np + 1], pL, &bH[2]);
                mma_bf16(o[2 * np + 1], pH, &bL[2]);
                mma_bf16(o[2 * np + 1], pH, &bH[2]);
            }
        }
        __syncthreads();
    }

    int b = bh / NH, h = bh - b * NH;
    float inv0 = 1.f / l0r, inv1 = 1.f / l1r;
    size_t row0 = (size_t)(b * NTOK + r0 + wm + g) * CDIM + h * HD;
    size_t row1 = (size_t)(b * NTOK + r0 + wm + 8 + g) * CDIM + h * HD;
    #pragma unroll
    for (int nb = 0; nb < 6; nb++) {
        int d = (nb << 3) + 2 * t;
        if (d < HD)     out[row0 + d]     = o[nb][0] * inv0;
        if (d + 1 < HD) out[row0 + d + 1] = o[nb][1] * inv0;
        if (d < HD)     out[row1 + d]     = o[nb][2] * inv1;
        if (d + 1 < HD) out[row1 + d + 1] = o[nb][3] * inv1;
    }
}

// ---------------------------------------------------------------------------
extern "C" void kernel_launch(void* const* d_in, const int* in_sizes, int n_in,
                              void* d_out, int out_size) {
    const float* x      = (const float*)d_in[0];
    const float* conv_w = (const float*)d_in[1];
    const float* conv_b = (const float*)d_in[2];
    const float* qkv_w  = (const float*)d_in[3];
    const float* qkv_b  = (const float*)d_in[4];
    float* out = (float*)d_out;

    cudaFuncSetAttribute(gemm_bf16_k<CDIM, false>,
                         cudaFuncAttributeMaxDynamicSharedMemorySize, GEMM_DSM);
    cudaFuncSetAttribute(gemm_bf16_k<QKVN, true>,
                         cudaFuncAttributeMaxDynamicSharedMemorySize, GEMM_DSM);
    cudaFuncSetAttribute(attn_k,
                         cudaFuncAttributeMaxDynamicSharedMemorySize, ATTN_DSM);

    patch_split_k<<<MTOT, 256>>>(x);
    weight_split_k<<<(CDIM * 294 + 255) / 256, 256>>>(conv_w, CDIM, 0);
    weight_split_k<<<(QKVN * 294 + 255) / 256, 256>>>(qkv_w, QKVN, 1);
    gemm_bf16_k<CDIM, false><<<dim3(NPAD1 / 128, MTOT / 128), 256, GEMM_DSM>>>(conv_b);
    gemm_bf16_k<QKVN, true ><<<dim3(NPAD2 / 128, MTOT / 128), 256, GEMM_DSM>>>(qkv_b);
    attn_k<<<dim3(NTOK / 128, BH), 256, ATTN_DSM>>>(out);
}